// round 15
// baseline (speedup 1.0000x reference)
#include <cuda_runtime.h>
#include <cuda_fp16.h>
#include <math.h>
#include <stdint.h>

// Problem constants
#define BSZ 2
#define SEQ 2048
#define DM  896
#define NL  24
#define NHQ 14
#define NHKV 2
#define DH  64
#define IFF 4864
#define ROWS (BSZ*SEQ)          // 4096
#define QKD (NHQ*DH)            // 896
#define KVD (NHKV*DH)           // 128
#define QKVD (QKD + 2*KVD)      // 1152
#define NGU (2*IFF)             // 9728 (interleaved gate|up)

// ---------------- scratch (device globals; no allocations allowed) ----------
__device__ float  g_x  [ROWS*DM];
__device__ __half g_h  [ROWS*DM];
__device__ __half g_qkv[(size_t)ROWS*QKVD];
__device__ __half g_ao [ROWS*QKD];
__device__ __half g_up [(size_t)ROWS*IFF];
// transposed (K-major) weights in fp16
__device__ __half g_wqkvT[(size_t)NL*QKVD*DM];
__device__ __half g_woT  [(size_t)NL*DM*QKD];
__device__ __half g_wguT [(size_t)NL*NGU*DM];   // rows interleaved: 2j=gate, 2j+1=up
__device__ __half g_wdT  [(size_t)NL*DM*IFF];
__device__ float  g_bqkv [NL*QKVD];
// rope tables
__device__ float  g_rc[SEQ*32];
__device__ float  g_rs[SEQ*32];

// ---------------- PTX helpers ----------------
__device__ __forceinline__ uint32_t smem_u32(const void* p) {
    uint32_t a;
    asm("{ .reg .u64 t; cvta.to.shared.u64 t, %1; cvt.u32.u64 %0, t; }" : "=r"(a) : "l"(p));
    return a;
}
__device__ __forceinline__ void cp_async16(uint32_t s, const void* g) {
    asm volatile("cp.async.cg.shared.global [%0], [%1], 16;\n" :: "r"(s), "l"(g));
}
__device__ __forceinline__ void cp_commit() { asm volatile("cp.async.commit_group;\n" ::: "memory"); }
template <int N>
__device__ __forceinline__ void cp_wait() { asm volatile("cp.async.wait_group %0;\n" :: "n"(N) : "memory"); }

__device__ __forceinline__ void mma16(float* c, const uint32_t* a, const uint32_t* b) {
    asm volatile(
        "mma.sync.aligned.m16n8k16.row.col.f32.f16.f16.f32 "
        "{%0,%1,%2,%3}, {%4,%5,%6,%7}, {%8,%9}, {%0,%1,%2,%3};"
        : "+f"(c[0]), "+f"(c[1]), "+f"(c[2]), "+f"(c[3])
        : "r"(a[0]), "r"(a[1]), "r"(a[2]), "r"(a[3]), "r"(b[0]), "r"(b[1]));
}
__device__ __forceinline__ void ldsm4(uint32_t* r, uint32_t addr) {
    asm volatile("ldmatrix.sync.aligned.m8n8.x4.shared.b16 {%0,%1,%2,%3}, [%4];"
        : "=r"(r[0]), "=r"(r[1]), "=r"(r[2]), "=r"(r[3]) : "r"(addr));
}
__device__ __forceinline__ uint32_t pack2(float a, float b) {
    __half2 h = __floats2half2_rn(a, b);
    return *(uint32_t*)&h;
}

// ---------------- elementwise copy ----------------
__global__ void copy_k(float* __restrict__ dst, const float* __restrict__ src, int n) {
    int i = blockIdx.x * blockDim.x + threadIdx.x;
    if (i < n) dst[i] = src[i];
}

// ---------------- rope tables ----------------
__global__ void ropetab_k(float* __restrict__ rc, float* __restrict__ rs) {
    int s = blockIdx.x, i = threadIdx.x;
    float inv = 1.0f / powf(1.0e6f, (float)i / 32.0f);
    float ang = (float)s * inv;
    rc[s * 32 + i] = cosf(ang);
    rs[s * 32 + i] = sinf(ang);
}

// ---------------- bias pack: [bq | bk | bv] per layer ----------------
__global__ void biaspack_k(const float* __restrict__ bq, const float* __restrict__ bk,
                           const float* __restrict__ bv, float* __restrict__ out) {
    int i = blockIdx.x * blockDim.x + threadIdx.x;
    if (i >= NL * QKVD) return;
    int l = i / QKVD, c = i % QKVD;
    float v;
    if (c < QKD) v = bq[l * QKD + c];
    else if (c < QKD + KVD) v = bk[l * KVD + c - QKD];
    else v = bv[l * KVD + c - QKD - KVD];
    out[i] = v;
}

// -------- transpose + fp16 round: out[z][rowMul*c+rowOff][r] = h(in[z][r][c])
__global__ __launch_bounds__(256) void transpose_k(const float* __restrict__ in,
                                                   __half* __restrict__ out,
                                                   int R, int C,
                                                   size_t inLS, size_t outLS,
                                                   int rowMul, int rowOff) {
    __shared__ float t[32][33];
    const float* ip = in + (size_t)blockIdx.z * inLS;
    __half* op = out + (size_t)blockIdx.z * outLS;
    int r0 = blockIdx.y * 32, c0 = blockIdx.x * 32;
    int tx = threadIdx.x & 31, ty = threadIdx.x >> 5;
#pragma unroll
    for (int i = 0; i < 32; i += 8)
        t[ty + i][tx] = ip[(size_t)(r0 + ty + i) * C + c0 + tx];
    __syncthreads();
#pragma unroll
    for (int i = 0; i < 32; i += 8)
        op[(size_t)((c0 + ty + i) * rowMul + rowOff) * R + r0 + tx] =
            __float2half_rn(t[tx][ty + i]);
}

// ---------------- RMSNorm (float4 vectorized) ----------------
template <typename OT>
__global__ __launch_bounds__(256) void rmsnorm_k(const float* __restrict__ x,
                                                 const float* __restrict__ w,
                                                 OT* __restrict__ o) {
    int row = blockIdx.x;
    const float* xr = x + (size_t)row * DM;
    float s = 0.f;
    for (int i = threadIdx.x * 4; i < DM; i += 1024) {
        float4 v = *(const float4*)(xr + i);
        s += v.x * v.x + v.y * v.y + v.z * v.z + v.w * v.w;
    }
    __shared__ float red[256];
    red[threadIdx.x] = s;
    __syncthreads();
    for (int st = 128; st > 0; st >>= 1) {
        if (threadIdx.x < st) red[threadIdx.x] += red[threadIdx.x + st];
        __syncthreads();
    }
    float r = rsqrtf(red[0] / (float)DM + 1e-6f);
    OT* orow = o + (size_t)row * DM;
    for (int i = threadIdx.x * 4; i < DM; i += 1024) {
        float4 v = *(const float4*)(xr + i);
        float4 wv = *(const float4*)(w + i);
        float o0 = v.x * r * wv.x, o1 = v.y * r * wv.y;
        float o2 = v.z * r * wv.z, o3 = v.w * r * wv.w;
        if (sizeof(OT) == 2) {
            __half2 h0 = __floats2half2_rn(o0, o1);
            __half2 h1 = __floats2half2_rn(o2, o3);
            *(__half2*)((__half*)orow + i)     = h0;
            *(__half2*)((__half*)orow + i + 2) = h1;
        } else {
            *(float4*)((float*)orow + i) = make_float4(o0, o1, o2, o3);
        }
    }
}

// ---------------- fp16 mma GEMM: C[M,N] = A[M,K] @ Bt[N,K]^T ----------------
// EPI 0: C = acc + bias (CT float or half) ; EPI 1: C(f32) += acc ;
// EPI 3: Bt rows interleave gate/up -> C(f16)[r][cg/2] = h(silu(v0)*v1)
#define PH 40                     // halves per smem row
#define STG_H (128 * PH)          // halves per A (or B) stage
template <int EPI, typename CT>
__global__ __launch_bounds__(256, 2) void mgemm_k(const __half* __restrict__ A,
                                                  const __half* __restrict__ Bt,
                                                  const float* __restrict__ bias,
                                                  CT* __restrict__ C,
                                                  int M, int N, int K) {
    extern __shared__ __half smemh[];
    uint32_t sbase = smem_u32(smemh);

    int tid = threadIdx.x;
    int wid = tid >> 5;
    int lane = tid & 31;
    int gid = lane >> 2, t4 = lane & 3;
    int wm = wid & 1, wn = wid >> 1;
    int row0 = blockIdx.y * 128, col0 = blockIdx.x * 128;

    const int NK = K >> 5;
    float acc[4][4][4] = {};

    uint32_t aoff[4];
#pragma unroll
    for (int mt = 0; mt < 4; mt++)
        aoff[mt] = (uint32_t)(((wm * 64 + mt * 16 + (lane & 15)) * PH
                               + ((lane >> 4) * 8)) * 2);
    uint32_t boff[2];
#pragma unroll
    for (int j = 0; j < 2; j++)
        boff[j] = (uint32_t)(((wn * 32 + j * 16 + (lane & 7) + ((lane & 16) ? 8 : 0)) * PH
                              + (((lane >> 3) & 1) * 8)) * 2);

    int lr = tid >> 2, lc = tid & 3;
    uint32_t loff = (uint32_t)(lr * PH + lc * 8) * 2;
    const __half* Ag  = A  + (size_t)(row0 + lr) * K + lc * 8;
    const __half* Bg  = Bt + (size_t)(col0 + lr) * K + lc * 8;
    const __half* Ag2 = Ag + 64 * K;
    const __half* Bg2 = Bg + 64 * K;
    uint32_t loff2 = loff + (uint32_t)(64 * PH) * 2;

#define PREFETCH(stg, k0)                                             \
    do {                                                              \
        uint32_t sa = sbase + (stg) * (2 * STG_H * 2);                \
        uint32_t sb = sa + STG_H * 2;                                 \
        cp_async16(sa + loff,  Ag  + (k0));                           \
        cp_async16(sa + loff2, Ag2 + (k0));                           \
        cp_async16(sb + loff,  Bg  + (k0));                           \
        cp_async16(sb + loff2, Bg2 + (k0));                           \
    } while (0)

    PREFETCH(0, 0);  cp_commit();
    PREFETCH(1, 32); cp_commit();
    PREFETCH(2, 64); cp_commit();

    for (int kt = 0; kt < NK; kt++) {
        if (kt + 3 < NK) cp_wait<2>(); else cp_wait<0>();
        __syncthreads();
        if (kt + 3 < NK) {
            PREFETCH((kt + 3) & 3, (kt + 3) << 5);
            cp_commit();
        }
        int s = kt & 3;
        uint32_t sa = sbase + s * (2 * STG_H * 2);
        uint32_t sb = sa + STG_H * 2;
#pragma unroll
        for (int ks = 0; ks < 2; ks++) {
            uint32_t ko = ks * 32;
            uint32_t af[4][4];
#pragma unroll
            for (int mt = 0; mt < 4; mt++)
                ldsm4(af[mt], sa + aoff[mt] + ko);
            uint32_t bq0[4], bq1[4];
            ldsm4(bq0, sb + boff[0] + ko);
            ldsm4(bq1, sb + boff[1] + ko);
#pragma unroll
            for (int mt = 0; mt < 4; mt++) {
                mma16(acc[mt][0], af[mt], &bq0[0]);
                mma16(acc[mt][1], af[mt], &bq0[2]);
                mma16(acc[mt][2], af[mt], &bq1[0]);
                mma16(acc[mt][3], af[mt], &bq1[2]);
            }
        }
    }
#undef PREFETCH

#pragma unroll
    for (int mt = 0; mt < 4; mt++) {
#pragma unroll
        for (int nt = 0; nt < 4; nt++) {
            int rg = row0 + wm * 64 + mt * 16 + gid;
            int cg = col0 + wn * 32 + nt * 8 + 2 * t4;
#pragma unroll
            for (int half = 0; half < 2; half++) {
                int r = rg + half * 8;
                float v0 = acc[mt][nt][half * 2 + 0];
                float v1 = acc[mt][nt][half * 2 + 1];
                if (EPI == 0) {
                    size_t idx = (size_t)r * N + cg;
                    float b0 = bias ? bias[cg] : 0.f;
                    float b1 = bias ? bias[cg + 1] : 0.f;
                    if (sizeof(CT) == 2) {
                        __half2 hv = __floats2half2_rn(v0 + b0, v1 + b1);
                        *(__half2*)((__half*)C + idx) = hv;
                    } else {
                        *(float2*)((float*)C + idx) = make_float2(v0 + b0, v1 + b1);
                    }
                } else if (EPI == 1) {
                    size_t idx = (size_t)r * N + cg;
                    float2 o = *(float2*)((float*)C + idx);
                    o.x += v0; o.y += v1;
                    *(float2*)((float*)C + idx) = o;
                } else {
                    size_t idx = (size_t)r * (N >> 1) + (cg >> 1);
                    float gv = v0 * (1.f / (1.f + expf(-v0))) * v1;
                    ((__half*)C)[idx] = __float2half_rn(gv);
                }
            }
        }
    }
}

// ---------------- Attention: FA2 tensor-core kernel, rope fused, fp16 qkv ---
#define PKH 72
__global__ __launch_bounds__(256) void attn_k(const __half* __restrict__ qkv,
                                              const int* __restrict__ tt,
                                              const float* __restrict__ am,
                                              const float* __restrict__ rc,
                                              const float* __restrict__ rs,
                                              __half* __restrict__ out) {
    __shared__ __half Ks [64][PKH];
    __shared__ __half VsT[64][PKH];
    __shared__ __half qsh[128][PKH];
    __shared__ int    tts[64];
    __shared__ float  padf[64];

    int b = blockIdx.z, h = blockIdx.y;
    int tid = threadIdx.x;
    int w = tid >> 5;
    int lane = tid & 31;
    int gid = lane >> 2, t4 = lane & 3;
    int qt0 = blockIdx.x * 128;
    int kvh = h / (NHQ / NHKV);
    int bS = b * SEQ;
    const float NEG = -3.0e38f;
    const float scale = 0.125f;

    uint32_t ksb = smem_u32(&Ks[0][0]);
    uint32_t vsb = smem_u32(&VsT[0][0]);
    uint32_t lboff[4];
#pragma unroll
    for (int j = 0; j < 4; j++)
        lboff[j] = (uint32_t)(((j * 16 + (lane & 7) + ((lane & 16) ? 8 : 0)) * PKH
                               + (((lane >> 3) & 1) * 8)) * 2);

    // ---- load Q tile with fused rope ----
    for (int idx = tid; idx < 128 * 8; idx += 256) {
        int r = idx >> 3, c4 = (idx & 7) * 4;
        int s = qt0 + r;
        const __half* qb_ = qkv + (size_t)(bS + s) * QKVD + h * 64;
        float2 a0 = __half22float2(*(const __half2*)(qb_ + c4));
        float2 a1 = __half22float2(*(const __half2*)(qb_ + c4 + 2));
        float2 b0 = __half22float2(*(const __half2*)(qb_ + c4 + 32));
        float2 b1 = __half22float2(*(const __half2*)(qb_ + c4 + 34));
        float4 cs = *(const float4*)(rc + s * 32 + c4);
        float4 sn = *(const float4*)(rs + s * 32 + c4);
        *(__half2*)&qsh[r][c4]      = __floats2half2_rn(a0.x*cs.x - b0.x*sn.x, a0.y*cs.y - b0.y*sn.y);
        *(__half2*)&qsh[r][c4 + 2]  = __floats2half2_rn(a1.x*cs.z - b1.x*sn.z, a1.y*cs.w - b1.y*sn.w);
        *(__half2*)&qsh[r][c4 + 32] = __floats2half2_rn(b0.x*cs.x + a0.x*sn.x, b0.y*cs.y + a0.y*sn.y);
        *(__half2*)&qsh[r][c4 + 34] = __floats2half2_rn(b1.x*cs.z + a1.x*sn.z, b1.y*cs.w + a1.y*sn.w);
    }
    __syncthreads();

    int qb = w * 16;
    uint32_t qf[4][4];
#pragma unroll
    for (int kc = 0; kc < 4; kc++) {
        int k0 = kc * 16 + 2 * t4;
        qf[kc][0] = *(const uint32_t*)&qsh[qb + gid][k0];
        qf[kc][1] = *(const uint32_t*)&qsh[qb + gid + 8][k0];
        qf[kc][2] = *(const uint32_t*)&qsh[qb + gid][k0 + 8];
        qf[kc][3] = *(const uint32_t*)&qsh[qb + gid + 8][k0 + 8];
    }

    int qi0 = qt0 + qb + gid, qi1 = qi0 + 8;
    int tq0 = tt[bS + qi0], tq1 = tt[bS + qi1];

    float m0 = -INFINITY, m1 = -INFINITY, l0 = 0.f, l1 = 0.f;
    float o[8][4];
#pragma unroll
    for (int dt = 0; dt < 8; dt++) { o[dt][0] = 0.f; o[dt][1] = 0.f; o[dt][2] = 0.f; o[dt][3] = 0.f; }

    for (int kt = 0; kt < SEQ; kt += 64) {
        __syncthreads();
        // K tile with fused rope
        for (int idx = tid; idx < 64 * 8; idx += 256) {
            int r = idx >> 3, c4 = (idx & 7) * 4;
            int s = kt + r;
            const __half* kb_ = qkv + (size_t)(bS + s) * QKVD + QKD + kvh * 64;
            float2 a0 = __half22float2(*(const __half2*)(kb_ + c4));
            float2 a1 = __half22float2(*(const __half2*)(kb_ + c4 + 2));
            float2 b0 = __half22float2(*(const __half2*)(kb_ + c4 + 32));
            float2 b1 = __half22float2(*(const __half2*)(kb_ + c4 + 34));
            float4 cs = *(const float4*)(rc + s * 32 + c4);
            float4 sn = *(const float4*)(rs + s * 32 + c4);
            *(__half2*)&Ks[r][c4]      = __floats2half2_rn(a0.x*cs.x - b0.x*sn.x, a0.y*cs.y - b0.y*sn.y);
            *(__half2*)&Ks[r][c4 + 2]  = __floats2half2_rn(a1.x*cs.z - b1.x*sn.z, a1.y*cs.w - b1.y*sn.w);
            *(__half2*)&Ks[r][c4 + 32] = __floats2half2_rn(b0.x*cs.x + a0.x*sn.x, b0.y*cs.y + a0.y*sn.y);
            *(__half2*)&Ks[r][c4 + 34] = __floats2half2_rn(b1.x*cs.z + a1.x*sn.z, b1.y*cs.w + a1.y*sn.w);
        }
        // V tile transposed (pure half repack, no conversion)
        for (int idx = tid; idx < 32 * 16; idx += 256) {
            int rp = idx >> 4, c4 = (idx & 15) * 4;
            int r = rp * 2;
            const __half* vb = qkv + (size_t)(bS + kt + r) * QKVD + QKD + KVD + kvh * 64;
            __half2 a01 = *(const __half2*)(vb + c4);
            __half2 a23 = *(const __half2*)(vb + c4 + 2);
            __half2 c01 = *(const __half2*)(vb + QKVD + c4);
            __half2 c23 = *(const __half2*)(vb + QKVD + c4 + 2);
            *(__half2*)&VsT[c4 + 0][r] = __halves2half2(__low2half(a01),  __low2half(c01));
            *(__half2*)&VsT[c4 + 1][r] = __halves2half2(__high2half(a01), __high2half(c01));
            *(__half2*)&VsT[c4 + 2][r] = __halves2half2(__low2half(a23),  __low2half(c23));
            *(__half2*)&VsT[c4 + 3][r] = __halves2half2(__high2half(a23), __high2half(c23));
        }
        if (tid < 64) {
            tts[tid]  = tt[bS + kt + tid];
            padf[tid] = (1.f - am[bS + kt + tid]) * NEG;
        }
        __syncthreads();

        float sc[8][4];
#pragma unroll
        for (int nt = 0; nt < 8; nt++) { sc[nt][0] = 0.f; sc[nt][1] = 0.f; sc[nt][2] = 0.f; sc[nt][3] = 0.f; }
#pragma unroll
        for (int kc = 0; kc < 4; kc++) {
            uint32_t ko = kc * 32;
            uint32_t kq[4][4];
#pragma unroll
            for (int j = 0; j < 4; j++)
                ldsm4(kq[j], ksb + lboff[j] + ko);
#pragma unroll
            for (int j = 0; j < 4; j++) {
                mma16(sc[2 * j],     qf[kc], &kq[j][0]);
                mma16(sc[2 * j + 1], qf[kc], &kq[j][2]);
            }
        }

        float rx0 = -INFINITY, rx1 = -INFINITY;
#pragma unroll
        for (int nt = 0; nt < 8; nt++) {
            int c0 = nt * 8 + 2 * t4, c1 = c0 + 1;
            int tk0 = tts[c0], tk1 = tts[c1];
            float pd0 = padf[c0], pd1 = padf[c1];
            int ki0 = kt + c0, ki1 = kt + c1;
            bool a00 = (tq0 == 0) ? (tk0 == 0) : ((tk0 == 0) || (ki0 <= qi0));
            bool a01 = (tq0 == 0) ? (tk1 == 0) : ((tk1 == 0) || (ki1 <= qi0));
            bool a10 = (tq1 == 0) ? (tk0 == 0) : ((tk0 == 0) || (ki0 <= qi1));
            bool a11 = (tq1 == 0) ? (tk1 == 0) : ((tk1 == 0) || (ki1 <= qi1));
            sc[nt][0] = fmaxf(sc[nt][0] * scale + (a00 ? 0.f : NEG) + pd0, -3.3e38f);
            sc[nt][1] = fmaxf(sc[nt][1] * scale + (a01 ? 0.f : NEG) + pd1, -3.3e38f);
            sc[nt][2] = fmaxf(sc[nt][2] * scale + (a10 ? 0.f : NEG) + pd0, -3.3e38f);
            sc[nt][3] = fmaxf(sc[nt][3] * scale + (a11 ? 0.f : NEG) + pd1, -3.3e38f);
            rx0 = fmaxf(rx0, fmaxf(sc[nt][0], sc[nt][1]));
            rx1 = fmaxf(rx1, fmaxf(sc[nt][2], sc[nt][3]));
        }
        rx0 = fmaxf(rx0, __shfl_xor_sync(0xffffffffu, rx0, 1));
        rx0 = fmaxf(rx0, __shfl_xor_sync(0xffffffffu, rx0, 2));
        rx1 = fmaxf(rx1, __shfl_xor_sync(0xffffffffu, rx1, 1));
        rx1 = fmaxf(rx1, __shfl_xor_sync(0xffffffffu, rx1, 2));

        float mn0 = fmaxf(m0, rx0), mn1 = fmaxf(m1, rx1);
        float corr0 = __expf(m0 - mn0), corr1 = __expf(m1 - mn1);

        float rs0 = 0.f, rs1 = 0.f;
#pragma unroll
        for (int nt = 0; nt < 8; nt++) {
            sc[nt][0] = __expf(sc[nt][0] - mn0);
            sc[nt][1] = __expf(sc[nt][1] - mn0);
            sc[nt][2] = __expf(sc[nt][2] - mn1);
            sc[nt][3] = __expf(sc[nt][3] - mn1);
            rs0 += sc[nt][0] + sc[nt][1];
            rs1 += sc[nt][2] + sc[nt][3];
        }
        rs0 += __shfl_xor_sync(0xffffffffu, rs0, 1);
        rs0 += __shfl_xor_sync(0xffffffffu, rs0, 2);
        rs1 += __shfl_xor_sync(0xffffffffu, rs1, 1);
        rs1 += __shfl_xor_sync(0xffffffffu, rs1, 2);
        l0 = l0 * corr0 + rs0;
        l1 = l1 * corr1 + rs1;
        m0 = mn0; m1 = mn1;

#pragma unroll
        for (int dt = 0; dt < 8; dt++) {
            o[dt][0] *= corr0; o[dt][1] *= corr0;
            o[dt][2] *= corr1; o[dt][3] *= corr1;
        }
        uint32_t pf[4][4];
#pragma unroll
        for (int kc = 0; kc < 4; kc++) {
            pf[kc][0] = pack2(sc[2 * kc][0], sc[2 * kc][1]);
            pf[kc][1] = pack2(sc[2 * kc][2], sc[2 * kc][3]);
            pf[kc][2] = pack2(sc[2 * kc + 1][0], sc[2 * kc + 1][1]);
            pf[kc][3] = pack2(sc[2 * kc + 1][2], sc[2 * kc + 1][3]);
        }
#pragma unroll
        for (int kc = 0; kc < 4; kc++) {
            uint32_t ko = kc * 32;
            uint32_t vq[4][4];
#pragma unroll
            for (int j = 0; j < 4; j++)
                ldsm4(vq[j], vsb + lboff[j] + ko);
#pragma unroll
            for (int j = 0; j < 4; j++) {
                mma16(o[2 * j],     pf[kc], &vq[j][0]);
                mma16(o[2 * j + 1], pf[kc], &vq[j][2]);
            }
        }
    }

    float il0 = 1.0f / l0, il1 = 1.0f / l1;
    __half* r0p = out + (size_t)(bS + qi0) * QKD + h * 64;
    __half* r1p = out + (size_t)(bS + qi1) * QKD + h * 64;
#pragma unroll
    for (int dt = 0; dt < 8; dt++) {
        int d0 = dt * 8 + 2 * t4;
        *(__half2*)(r0p + d0) = __floats2half2_rn(o[dt][0] * il0, o[dt][1] * il0);
        *(__half2*)(r1p + d0) = __floats2half2_rn(o[dt][2] * il1, o[dt][3] * il1);
    }
}

// ---------------- host driver ----------------
extern "C" void kernel_launch(void* const* d_in, const int* in_sizes, int n_in,
                              void* d_out, int out_size) {
    const float* emb = (const float*)d_in[0];
    const int*   tt  = (const int*)  d_in[1];
    const float* am  = (const float*)d_in[2];
    const float* wq  = (const float*)d_in[3];
    const float* bq  = (const float*)d_in[4];
    const float* wk  = (const float*)d_in[5];
    const float* bk  = (const float*)d_in[6];
    const float* wv  = (const float*)d_in[7];
    const float* bv  = (const float*)d_in[8];
    const float* wo  = (const float*)d_in[9];
    const float* wg  = (const float*)d_in[10];
    const float* wu  = (const float*)d_in[11];
    const float* wd  = (const float*)d_in[12];
    const float* ln1 = (const float*)d_in[13];
    const float* ln2 = (const float*)d_in[14];
    const float* lnf = (const float*)d_in[15];

    float *x, *bqkv, *rc, *rs;
    __half *h, *qkv, *ao, *up, *wqkvT, *woT, *wguT, *wdT;
    cudaGetSymbolAddress((void**)&x,   g_x);
    cudaGetSymbolAddress((void**)&h,   g_h);
    cudaGetSymbolAddress((void**)&qkv, g_qkv);
    cudaGetSymbolAddress((void**)&ao,  g_ao);
    cudaGetSymbolAddress((void**)&up,  g_up);
    cudaGetSymbolAddress((void**)&wqkvT, g_wqkvT);
    cudaGetSymbolAddress((void**)&woT, g_woT);
    cudaGetSymbolAddress((void**)&wguT, g_wguT);
    cudaGetSymbolAddress((void**)&wdT, g_wdT);
    cudaGetSymbolAddress((void**)&bqkv, g_bqkv);
    cudaGetSymbolAddress((void**)&rc, g_rc);
    cudaGetSymbolAddress((void**)&rs, g_rs);

    const int GSMEM = 4 * 2 * STG_H * 2;   // 81920 bytes
    cudaFuncSetAttribute(mgemm_k<0, __half>, cudaFuncAttributeMaxDynamicSharedMemorySize, GSMEM);
    cudaFuncSetAttribute(mgemm_k<1, float>,  cudaFuncAttributeMaxDynamicSharedMemorySize, GSMEM);
    cudaFuncSetAttribute(mgemm_k<3, __half>, cudaFuncAttributeMaxDynamicSharedMemorySize, GSMEM);

    // weight transposes (+fp16 rounding)
    size_t oLS = (size_t)QKVD * DM;
    transpose_k<<<dim3(QKD/32, DM/32, NL), 256>>>(wq, wqkvT,            DM, QKD, (size_t)DM*QKD, oLS, 1, 0);
    transpose_k<<<dim3(KVD/32, DM/32, NL), 256>>>(wk, wqkvT + (size_t)QKD*DM,       DM, KVD, (size_t)DM*KVD, oLS, 1, 0);
    transpose_k<<<dim3(KVD/32, DM/32, NL), 256>>>(wv, wqkvT + (size_t)(QKD+KVD)*DM, DM, KVD, (size_t)DM*KVD, oLS, 1, 0);
    transpose_k<<<dim3(DM/32, QKD/32, NL), 256>>>(wo, woT, QKD, DM, (size_t)QKD*DM, (size_t)DM*QKD, 1, 0);
    transpose_k<<<dim3(IFF/32, DM/32, NL), 256>>>(wg, wguT, DM, IFF, (size_t)DM*IFF, (size_t)NGU*DM, 2, 0);
    transpose_k<<<dim3(IFF/32, DM/32, NL), 256>>>(wu, wguT, DM, IFF, (size_t)DM*IFF, (size_t)NGU*DM, 2, 1);
    transpose_k<<<dim3(DM/32, IFF/32, NL), 256>>>(wd, wdT, IFF, DM, (size_t)IFF*DM, (size_t)DM*IFF, 1, 0);
    biaspack_k<<<(NL*QKVD + 255)/256, 256>>>(bq, bk, bv, bqkv);
    ropetab_k<<<SEQ, 32>>>(rc, rs);

    int nx = ROWS * DM;
    copy_k<<<(nx + 255) / 256, 256>>>(x, emb, nx);

    dim3 gQKV(QKVD / 128, ROWS / 128);   // (9, 32)
    dim3 gDM (DM   / 128, ROWS / 128);   // (7, 32)
    dim3 gGU (NGU  / 128, ROWS / 128);   // (76, 32)
    dim3 gAt (SEQ / 128, NHQ, BSZ);      // (16, 14, 2)

    for (int l = 0; l < NL; l++) {
        rmsnorm_k<__half><<<ROWS, 256>>>(x, ln1 + (size_t)l * DM, h);

        mgemm_k<0, __half><<<gQKV, 256, GSMEM>>>(h, wqkvT + (size_t)l * QKVD * DM,
                                                 bqkv + (size_t)l * QKVD, qkv,
                                                 ROWS, QKVD, DM);

        attn_k<<<gAt, 256>>>(qkv, tt, am, rc, rs, ao);

        mgemm_k<1, float><<<gDM, 256, GSMEM>>>(ao, woT + (size_t)l * DM * QKD,
                                               nullptr, x, ROWS, DM, QKD);

        rmsnorm_k<__half><<<ROWS, 256>>>(x, ln2 + (size_t)l * DM, h);

        mgemm_k<3, __half><<<gGU, 256, GSMEM>>>(h, wguT + (size_t)l * NGU * DM,
                                                nullptr, up, ROWS, NGU, DM);
        mgemm_k<1, float><<<gDM, 256, GSMEM>>>(up, wdT + (size_t)l * DM * IFF,
                                               nullptr, x, ROWS, DM, IFF);
    }

    rmsnorm_k<float><<<ROWS, 256>>>(x, lnf, (float*)d_out);
}

// round 16
// speedup vs baseline: 1.5558x; 1.5558x over previous
#include <cuda_runtime.h>
#include <cuda_fp16.h>
#include <math.h>
#include <stdint.h>

// Problem constants
#define BSZ 2
#define SEQ 2048
#define DM  896
#define NL  24
#define NHQ 14
#define NHKV 2
#define DH  64
#define IFF 4864
#define ROWS (BSZ*SEQ)          // 4096
#define QKD (NHQ*DH)            // 896
#define KVD (NHKV*DH)           // 128
#define QKVD (QKD + 2*KVD)      // 1152
#define NGU (2*IFF)             // 9728 (interleaved gate|up)

// ---------------- scratch (device globals; no allocations allowed) ----------
__device__ float  g_x  [ROWS*DM];
__device__ __half g_h  [ROWS*DM];
__device__ float  g_qkv[(size_t)ROWS*QKVD];
__device__ __half g_ao [ROWS*QKD];
__device__ __half g_up [(size_t)ROWS*IFF];
// transposed (K-major) weights in fp16
__device__ __half g_wqkvT[(size_t)NL*QKVD*DM];
__device__ __half g_woT  [(size_t)NL*DM*QKD];
__device__ __half g_wguT [(size_t)NL*NGU*DM];   // rows interleaved: 2j=gate, 2j+1=up
__device__ __half g_wdT  [(size_t)NL*DM*IFF];
__device__ float  g_bqkv [NL*QKVD];
// rope tables
__device__ float  g_rc[SEQ*32];
__device__ float  g_rs[SEQ*32];

// ---------------- PTX helpers ----------------
__device__ __forceinline__ uint32_t smem_u32(const void* p) {
    uint32_t a;
    asm("{ .reg .u64 t; cvta.to.shared.u64 t, %1; cvt.u32.u64 %0, t; }" : "=r"(a) : "l"(p));
    return a;
}
__device__ __forceinline__ void cp_async16(uint32_t s, const void* g) {
    asm volatile("cp.async.cg.shared.global [%0], [%1], 16;\n" :: "r"(s), "l"(g));
}
__device__ __forceinline__ void cp_commit() { asm volatile("cp.async.commit_group;\n" ::: "memory"); }
template <int N>
__device__ __forceinline__ void cp_wait() { asm volatile("cp.async.wait_group %0;\n" :: "n"(N) : "memory"); }

__device__ __forceinline__ void mma16(float* c, const uint32_t* a, const uint32_t* b) {
    asm volatile(
        "mma.sync.aligned.m16n8k16.row.col.f32.f16.f16.f32 "
        "{%0,%1,%2,%3}, {%4,%5,%6,%7}, {%8,%9}, {%0,%1,%2,%3};"
        : "+f"(c[0]), "+f"(c[1]), "+f"(c[2]), "+f"(c[3])
        : "r"(a[0]), "r"(a[1]), "r"(a[2]), "r"(a[3]), "r"(b[0]), "r"(b[1]));
}
__device__ __forceinline__ void ldsm4(uint32_t* r, uint32_t addr) {
    asm volatile("ldmatrix.sync.aligned.m8n8.x4.shared.b16 {%0,%1,%2,%3}, [%4];"
        : "=r"(r[0]), "=r"(r[1]), "=r"(r[2]), "=r"(r[3]) : "r"(addr));
}
__device__ __forceinline__ uint32_t pack2(float a, float b) {
    __half2 h = __floats2half2_rn(a, b);
    return *(uint32_t*)&h;
}

// ---------------- elementwise copy ----------------
__global__ void copy_k(float* __restrict__ dst, const float* __restrict__ src, int n) {
    int i = blockIdx.x * blockDim.x + threadIdx.x;
    if (i < n) dst[i] = src[i];
}

// ---------------- rope tables ----------------
__global__ void ropetab_k(float* __restrict__ rc, float* __restrict__ rs) {
    int s = blockIdx.x, i = threadIdx.x;
    float inv = 1.0f / powf(1.0e6f, (float)i / 32.0f);
    float ang = (float)s * inv;
    rc[s * 32 + i] = cosf(ang);
    rs[s * 32 + i] = sinf(ang);
}

// ---------------- bias pack: [bq | bk | bv] per layer ----------------
__global__ void biaspack_k(const float* __restrict__ bq, const float* __restrict__ bk,
                           const float* __restrict__ bv, float* __restrict__ out) {
    int i = blockIdx.x * blockDim.x + threadIdx.x;
    if (i >= NL * QKVD) return;
    int l = i / QKVD, c = i % QKVD;
    float v;
    if (c < QKD) v = bq[l * QKD + c];
    else if (c < QKD + KVD) v = bk[l * KVD + c - QKD];
    else v = bv[l * KVD + c - QKD - KVD];
    out[i] = v;
}

// -------- transpose + fp16 round: out[z][rowMul*c+rowOff][r] = h(in[z][r][c])
__global__ __launch_bounds__(256) void transpose_k(const float* __restrict__ in,
                                                   __half* __restrict__ out,
                                                   int R, int C,
                                                   size_t inLS, size_t outLS,
                                                   int rowMul, int rowOff) {
    __shared__ float t[32][33];
    const float* ip = in + (size_t)blockIdx.z * inLS;
    __half* op = out + (size_t)blockIdx.z * outLS;
    int r0 = blockIdx.y * 32, c0 = blockIdx.x * 32;
    int tx = threadIdx.x & 31, ty = threadIdx.x >> 5;
#pragma unroll
    for (int i = 0; i < 32; i += 8)
        t[ty + i][tx] = ip[(size_t)(r0 + ty + i) * C + c0 + tx];
    __syncthreads();
#pragma unroll
    for (int i = 0; i < 32; i += 8)
        op[(size_t)((c0 + ty + i) * rowMul + rowOff) * R + r0 + tx] =
            __float2half_rn(t[tx][ty + i]);
}

// ---------------- RMSNorm (float4 vectorized) ----------------
template <typename OT>
__global__ __launch_bounds__(256) void rmsnorm_k(const float* __restrict__ x,
                                                 const float* __restrict__ w,
                                                 OT* __restrict__ o) {
    int row = blockIdx.x;
    const float* xr = x + (size_t)row * DM;
    float s = 0.f;
    for (int i = threadIdx.x * 4; i < DM; i += 1024) {
        float4 v = *(const float4*)(xr + i);
        s += v.x * v.x + v.y * v.y + v.z * v.z + v.w * v.w;
    }
    __shared__ float red[256];
    red[threadIdx.x] = s;
    __syncthreads();
    for (int st = 128; st > 0; st >>= 1) {
        if (threadIdx.x < st) red[threadIdx.x] += red[threadIdx.x + st];
        __syncthreads();
    }
    float r = rsqrtf(red[0] / (float)DM + 1e-6f);
    OT* orow = o + (size_t)row * DM;
    for (int i = threadIdx.x * 4; i < DM; i += 1024) {
        float4 v = *(const float4*)(xr + i);
        float4 wv = *(const float4*)(w + i);
        float o0 = v.x * r * wv.x, o1 = v.y * r * wv.y;
        float o2 = v.z * r * wv.z, o3 = v.w * r * wv.w;
        if (sizeof(OT) == 2) {
            __half2 h0 = __floats2half2_rn(o0, o1);
            __half2 h1 = __floats2half2_rn(o2, o3);
            *(__half2*)((__half*)orow + i)     = h0;
            *(__half2*)((__half*)orow + i + 2) = h1;
        } else {
            *(float4*)((float*)orow + i) = make_float4(o0, o1, o2, o3);
        }
    }
}

// ---------------- fp16 mma GEMM: C[M,N] = A[M,K] @ Bt[N,K]^T ----------------
// EPI 0: C = acc + bias (CT float or half) ; EPI 1: C(f32) += acc ;
// EPI 3: Bt rows interleave gate/up -> C(f16)[r][cg/2] = h(silu(v0)*v1)
#define PH 40                     // halves per smem row
#define STG_H (128 * PH)          // halves per A (or B) stage
template <int EPI, typename CT>
__global__ __launch_bounds__(256, 2) void mgemm_k(const __half* __restrict__ A,
                                                  const __half* __restrict__ Bt,
                                                  const float* __restrict__ bias,
                                                  CT* __restrict__ C,
                                                  int M, int N, int K) {
    extern __shared__ __half smemh[];
    uint32_t sbase = smem_u32(smemh);

    int tid = threadIdx.x;
    int wid = tid >> 5;
    int lane = tid & 31;
    int gid = lane >> 2, t4 = lane & 3;
    int wm = wid & 1, wn = wid >> 1;
    int row0 = blockIdx.y * 128, col0 = blockIdx.x * 128;

    const int NK = K >> 5;
    float acc[4][4][4] = {};

    uint32_t aoff[4];
#pragma unroll
    for (int mt = 0; mt < 4; mt++)
        aoff[mt] = (uint32_t)(((wm * 64 + mt * 16 + (lane & 15)) * PH
                               + ((lane >> 4) * 8)) * 2);
    uint32_t boff[2];
#pragma unroll
    for (int j = 0; j < 2; j++)
        boff[j] = (uint32_t)(((wn * 32 + j * 16 + (lane & 7) + ((lane & 16) ? 8 : 0)) * PH
                              + (((lane >> 3) & 1) * 8)) * 2);

    int lr = tid >> 2, lc = tid & 3;
    uint32_t loff = (uint32_t)(lr * PH + lc * 8) * 2;
    const __half* Ag  = A  + (size_t)(row0 + lr) * K + lc * 8;
    const __half* Bg  = Bt + (size_t)(col0 + lr) * K + lc * 8;
    const __half* Ag2 = Ag + 64 * K;
    const __half* Bg2 = Bg + 64 * K;
    uint32_t loff2 = loff + (uint32_t)(64 * PH) * 2;

#define PREFETCH(stg, k0)                                             \
    do {                                                              \
        uint32_t sa = sbase + (stg) * (2 * STG_H * 2);                \
        uint32_t sb = sa + STG_H * 2;                                 \
        cp_async16(sa + loff,  Ag  + (k0));                           \
        cp_async16(sa + loff2, Ag2 + (k0));                           \
        cp_async16(sb + loff,  Bg  + (k0));                           \
        cp_async16(sb + loff2, Bg2 + (k0));                           \
    } while (0)

    PREFETCH(0, 0);  cp_commit();
    PREFETCH(1, 32); cp_commit();
    PREFETCH(2, 64); cp_commit();

    for (int kt = 0; kt < NK; kt++) {
        if (kt + 3 < NK) cp_wait<2>(); else cp_wait<0>();
        __syncthreads();
        if (kt + 3 < NK) {
            PREFETCH((kt + 3) & 3, (kt + 3) << 5);
            cp_commit();
        }
        int s = kt & 3;
        uint32_t sa = sbase + s * (2 * STG_H * 2);
        uint32_t sb = sa + STG_H * 2;
#pragma unroll
        for (int ks = 0; ks < 2; ks++) {
            uint32_t ko = ks * 32;
            uint32_t af[4][4];
#pragma unroll
            for (int mt = 0; mt < 4; mt++)
                ldsm4(af[mt], sa + aoff[mt] + ko);
            uint32_t bq0[4], bq1[4];
            ldsm4(bq0, sb + boff[0] + ko);
            ldsm4(bq1, sb + boff[1] + ko);
#pragma unroll
            for (int mt = 0; mt < 4; mt++) {
                mma16(acc[mt][0], af[mt], &bq0[0]);
                mma16(acc[mt][1], af[mt], &bq0[2]);
                mma16(acc[mt][2], af[mt], &bq1[0]);
                mma16(acc[mt][3], af[mt], &bq1[2]);
            }
        }
    }
#undef PREFETCH

#pragma unroll
    for (int mt = 0; mt < 4; mt++) {
#pragma unroll
        for (int nt = 0; nt < 4; nt++) {
            int rg = row0 + wm * 64 + mt * 16 + gid;
            int cg = col0 + wn * 32 + nt * 8 + 2 * t4;
#pragma unroll
            for (int half = 0; half < 2; half++) {
                int r = rg + half * 8;
                float v0 = acc[mt][nt][half * 2 + 0];
                float v1 = acc[mt][nt][half * 2 + 1];
                if (EPI == 0) {
                    size_t idx = (size_t)r * N + cg;
                    float b0 = bias ? bias[cg] : 0.f;
                    float b1 = bias ? bias[cg + 1] : 0.f;
                    if (sizeof(CT) == 2) {
                        __half2 hv = __floats2half2_rn(v0 + b0, v1 + b1);
                        *(__half2*)((__half*)C + idx) = hv;
                    } else {
                        *(float2*)((float*)C + idx) = make_float2(v0 + b0, v1 + b1);
                    }
                } else if (EPI == 1) {
                    size_t idx = (size_t)r * N + cg;
                    float2 o = *(float2*)((float*)C + idx);
                    o.x += v0; o.y += v1;
                    *(float2*)((float*)C + idx) = o;
                } else {
                    size_t idx = (size_t)r * (N >> 1) + (cg >> 1);
                    float gv = v0 * (1.f / (1.f + expf(-v0))) * v1;
                    ((__half*)C)[idx] = __float2half_rn(gv);
                }
            }
        }
    }
}

// ---------------- Attention: FA2 tensor-core kernel, rope fused -------------
#define PKH 72
__global__ __launch_bounds__(256) void attn_k(const float* __restrict__ qkv,
                                              const int* __restrict__ tt,
                                              const float* __restrict__ am,
                                              const float* __restrict__ rc,
                                              const float* __restrict__ rs,
                                              __half* __restrict__ out) {
    __shared__ __half Ks [64][PKH];
    __shared__ __half VsT[64][PKH];
    __shared__ __half qsh[128][PKH];
    __shared__ int    tts[64];
    __shared__ float  padf[64];

    int b = blockIdx.z, h = blockIdx.y;
    int tid = threadIdx.x;
    int w = tid >> 5;
    int lane = tid & 31;
    int gid = lane >> 2, t4 = lane & 3;
    int qt0 = blockIdx.x * 128;
    int kvh = h / (NHQ / NHKV);
    int bS = b * SEQ;
    const float NEG = -3.0e38f;
    const float scale = 0.125f;

    uint32_t ksb = smem_u32(&Ks[0][0]);
    uint32_t vsb = smem_u32(&VsT[0][0]);
    uint32_t lboff[4];
#pragma unroll
    for (int j = 0; j < 4; j++)
        lboff[j] = (uint32_t)(((j * 16 + (lane & 7) + ((lane & 16) ? 8 : 0)) * PKH
                               + (((lane >> 3) & 1) * 8)) * 2);

    for (int idx = tid; idx < 128 * 8; idx += 256) {
        int r = idx >> 3, c4 = (idx & 7) * 4;
        int s = qt0 + r;
        const float* qb_ = qkv + (size_t)(bS + s) * QKVD + h * 64;
        float4 qa = *(const float4*)(qb_ + c4);
        float4 qc = *(const float4*)(qb_ + c4 + 32);
        float4 cs = *(const float4*)(rc + s * 32 + c4);
        float4 sn = *(const float4*)(rs + s * 32 + c4);
        *(__half2*)&qsh[r][c4]      = __floats2half2_rn(qa.x*cs.x - qc.x*sn.x, qa.y*cs.y - qc.y*sn.y);
        *(__half2*)&qsh[r][c4 + 2]  = __floats2half2_rn(qa.z*cs.z - qc.z*sn.z, qa.w*cs.w - qc.w*sn.w);
        *(__half2*)&qsh[r][c4 + 32] = __floats2half2_rn(qc.x*cs.x + qa.x*sn.x, qc.y*cs.y + qa.y*sn.y);
        *(__half2*)&qsh[r][c4 + 34] = __floats2half2_rn(qc.z*cs.z + qa.z*sn.z, qc.w*cs.w + qa.w*sn.w);
    }
    __syncthreads();

    int qb = w * 16;
    uint32_t qf[4][4];
#pragma unroll
    for (int kc = 0; kc < 4; kc++) {
        int k0 = kc * 16 + 2 * t4;
        qf[kc][0] = *(const uint32_t*)&qsh[qb + gid][k0];
        qf[kc][1] = *(const uint32_t*)&qsh[qb + gid + 8][k0];
        qf[kc][2] = *(const uint32_t*)&qsh[qb + gid][k0 + 8];
        qf[kc][3] = *(const uint32_t*)&qsh[qb + gid + 8][k0 + 8];
    }

    int qi0 = qt0 + qb + gid, qi1 = qi0 + 8;
    int tq0 = tt[bS + qi0], tq1 = tt[bS + qi1];

    float m0 = -INFINITY, m1 = -INFINITY, l0 = 0.f, l1 = 0.f;
    float o[8][4];
#pragma unroll
    for (int dt = 0; dt < 8; dt++) { o[dt][0] = 0.f; o[dt][1] = 0.f; o[dt][2] = 0.f; o[dt][3] = 0.f; }

    for (int kt = 0; kt < SEQ; kt += 64) {
        __syncthreads();
        for (int idx = tid; idx < 64 * 8; idx += 256) {
            int r = idx >> 3, c4 = (idx & 7) * 4;
            int s = kt + r;
            const float* kb_ = qkv + (size_t)(bS + s) * QKVD + QKD + kvh * 64;
            float4 ka = *(const float4*)(kb_ + c4);
            float4 kc_ = *(const float4*)(kb_ + c4 + 32);
            float4 cs = *(const float4*)(rc + s * 32 + c4);
            float4 sn = *(const float4*)(rs + s * 32 + c4);
            *(__half2*)&Ks[r][c4]      = __floats2half2_rn(ka.x*cs.x - kc_.x*sn.x, ka.y*cs.y - kc_.y*sn.y);
            *(__half2*)&Ks[r][c4 + 2]  = __floats2half2_rn(ka.z*cs.z - kc_.z*sn.z, ka.w*cs.w - kc_.w*sn.w);
            *(__half2*)&Ks[r][c4 + 32] = __floats2half2_rn(kc_.x*cs.x + ka.x*sn.x, kc_.y*cs.y + ka.y*sn.y);
            *(__half2*)&Ks[r][c4 + 34] = __floats2half2_rn(kc_.z*cs.z + ka.z*sn.z, kc_.w*cs.w + ka.w*sn.w);
        }
        for (int idx = tid; idx < 32 * 16; idx += 256) {
            int rp = idx >> 4, c4 = (idx & 15) * 4;
            int r = rp * 2;
            const float* vb = qkv + (size_t)(bS + kt + r) * QKVD + QKD + KVD + kvh * 64;
            float4 va = *(const float4*)(vb + c4);
            float4 vc = *(const float4*)(vb + QKVD + c4);
            *(__half2*)&VsT[c4 + 0][r] = __floats2half2_rn(va.x, vc.x);
            *(__half2*)&VsT[c4 + 1][r] = __floats2half2_rn(va.y, vc.y);
            *(__half2*)&VsT[c4 + 2][r] = __floats2half2_rn(va.z, vc.z);
            *(__half2*)&VsT[c4 + 3][r] = __floats2half2_rn(va.w, vc.w);
        }
        if (tid < 64) {
            tts[tid]  = tt[bS + kt + tid];
            padf[tid] = (1.f - am[bS + kt + tid]) * NEG;
        }
        __syncthreads();

        float sc[8][4];
#pragma unroll
        for (int nt = 0; nt < 8; nt++) { sc[nt][0] = 0.f; sc[nt][1] = 0.f; sc[nt][2] = 0.f; sc[nt][3] = 0.f; }
#pragma unroll
        for (int kc = 0; kc < 4; kc++) {
            uint32_t ko = kc * 32;
            uint32_t kq[4][4];
#pragma unroll
            for (int j = 0; j < 4; j++)
                ldsm4(kq[j], ksb + lboff[j] + ko);
#pragma unroll
            for (int j = 0; j < 4; j++) {
                mma16(sc[2 * j],     qf[kc], &kq[j][0]);
                mma16(sc[2 * j + 1], qf[kc], &kq[j][2]);
            }
        }

        float rx0 = -INFINITY, rx1 = -INFINITY;
#pragma unroll
        for (int nt = 0; nt < 8; nt++) {
            int c0 = nt * 8 + 2 * t4, c1 = c0 + 1;
            int tk0 = tts[c0], tk1 = tts[c1];
            float pd0 = padf[c0], pd1 = padf[c1];
            int ki0 = kt + c0, ki1 = kt + c1;
            bool a00 = (tq0 == 0) ? (tk0 == 0) : ((tk0 == 0) || (ki0 <= qi0));
            bool a01 = (tq0 == 0) ? (tk1 == 0) : ((tk1 == 0) || (ki1 <= qi0));
            bool a10 = (tq1 == 0) ? (tk0 == 0) : ((tk0 == 0) || (ki0 <= qi1));
            bool a11 = (tq1 == 0) ? (tk1 == 0) : ((tk1 == 0) || (ki1 <= qi1));
            sc[nt][0] = fmaxf(sc[nt][0] * scale + (a00 ? 0.f : NEG) + pd0, -3.3e38f);
            sc[nt][1] = fmaxf(sc[nt][1] * scale + (a01 ? 0.f : NEG) + pd1, -3.3e38f);
            sc[nt][2] = fmaxf(sc[nt][2] * scale + (a10 ? 0.f : NEG) + pd0, -3.3e38f);
            sc[nt][3] = fmaxf(sc[nt][3] * scale + (a11 ? 0.f : NEG) + pd1, -3.3e38f);
            rx0 = fmaxf(rx0, fmaxf(sc[nt][0], sc[nt][1]));
            rx1 = fmaxf(rx1, fmaxf(sc[nt][2], sc[nt][3]));
        }
        rx0 = fmaxf(rx0, __shfl_xor_sync(0xffffffffu, rx0, 1));
        rx0 = fmaxf(rx0, __shfl_xor_sync(0xffffffffu, rx0, 2));
        rx1 = fmaxf(rx1, __shfl_xor_sync(0xffffffffu, rx1, 1));
        rx1 = fmaxf(rx1, __shfl_xor_sync(0xffffffffu, rx1, 2));

        float mn0 = fmaxf(m0, rx0), mn1 = fmaxf(m1, rx1);
        float corr0 = __expf(m0 - mn0), corr1 = __expf(m1 - mn1);

        float rs0 = 0.f, rs1 = 0.f;
#pragma unroll
        for (int nt = 0; nt < 8; nt++) {
            sc[nt][0] = __expf(sc[nt][0] - mn0);
            sc[nt][1] = __expf(sc[nt][1] - mn0);
            sc[nt][2] = __expf(sc[nt][2] - mn1);
            sc[nt][3] = __expf(sc[nt][3] - mn1);
            rs0 += sc[nt][0] + sc[nt][1];
            rs1 += sc[nt][2] + sc[nt][3];
        }
        rs0 += __shfl_xor_sync(0xffffffffu, rs0, 1);
        rs0 += __shfl_xor_sync(0xffffffffu, rs0, 2);
        rs1 += __shfl_xor_sync(0xffffffffu, rs1, 1);
        rs1 += __shfl_xor_sync(0xffffffffu, rs1, 2);
        l0 = l0 * corr0 + rs0;
        l1 = l1 * corr1 + rs1;
        m0 = mn0; m1 = mn1;

#pragma unroll
        for (int dt = 0; dt < 8; dt++) {
            o[dt][0] *= corr0; o[dt][1] *= corr0;
            o[dt][2] *= corr1; o[dt][3] *= corr1;
        }
        uint32_t pf[4][4];
#pragma unroll
        for (int kc = 0; kc < 4; kc++) {
            pf[kc][0] = pack2(sc[2 * kc][0], sc[2 * kc][1]);
            pf[kc][1] = pack2(sc[2 * kc][2], sc[2 * kc][3]);
            pf[kc][2] = pack2(sc[2 * kc + 1][0], sc[2 * kc + 1][1]);
            pf[kc][3] = pack2(sc[2 * kc + 1][2], sc[2 * kc + 1][3]);
        }
#pragma unroll
        for (int kc = 0; kc < 4; kc++) {
            uint32_t ko = kc * 32;
            uint32_t vq[4][4];
#pragma unroll
            for (int j = 0; j < 4; j++)
                ldsm4(vq[j], vsb + lboff[j] + ko);
#pragma unroll
            for (int j = 0; j < 4; j++) {
                mma16(o[2 * j],     pf[kc], &vq[j][0]);
                mma16(o[2 * j + 1], pf[kc], &vq[j][2]);
            }
        }
    }

    float il0 = 1.0f / l0, il1 = 1.0f / l1;
    __half* r0p = out + (size_t)(bS + qi0) * QKD + h * 64;
    __half* r1p = out + (size_t)(bS + qi1) * QKD + h * 64;
#pragma unroll
    for (int dt = 0; dt < 8; dt++) {
        int d0 = dt * 8 + 2 * t4;
        *(__half2*)(r0p + d0) = __floats2half2_rn(o[dt][0] * il0, o[dt][1] * il0);
        *(__half2*)(r1p + d0) = __floats2half2_rn(o[dt][2] * il1, o[dt][3] * il1);
    }
}

// ---------------- host driver ----------------
extern "C" void kernel_launch(void* const* d_in, const int* in_sizes, int n_in,
                              void* d_out, int out_size) {
    const float* emb = (const float*)d_in[0];
    const int*   tt  = (const int*)  d_in[1];
    const float* am  = (const float*)d_in[2];
    const float* wq  = (const float*)d_in[3];
    const float* bq  = (const float*)d_in[4];
    const float* wk  = (const float*)d_in[5];
    const float* bk  = (const float*)d_in[6];
    const float* wv  = (const float*)d_in[7];
    const float* bv  = (const float*)d_in[8];
    const float* wo  = (const float*)d_in[9];
    const float* wg  = (const float*)d_in[10];
    const float* wu  = (const float*)d_in[11];
    const float* wd  = (const float*)d_in[12];
    const float* ln1 = (const float*)d_in[13];
    const float* ln2 = (const float*)d_in[14];
    const float* lnf = (const float*)d_in[15];

    float *x, *qkv, *bqkv, *rc, *rs;
    __half *h, *ao, *up, *wqkvT, *woT, *wguT, *wdT;
    cudaGetSymbolAddress((void**)&x,   g_x);
    cudaGetSymbolAddress((void**)&h,   g_h);
    cudaGetSymbolAddress((void**)&qkv, g_qkv);
    cudaGetSymbolAddress((void**)&ao,  g_ao);
    cudaGetSymbolAddress((void**)&up,  g_up);
    cudaGetSymbolAddress((void**)&wqkvT, g_wqkvT);
    cudaGetSymbolAddress((void**)&woT, g_woT);
    cudaGetSymbolAddress((void**)&wguT, g_wguT);
    cudaGetSymbolAddress((void**)&wdT, g_wdT);
    cudaGetSymbolAddress((void**)&bqkv, g_bqkv);
    cudaGetSymbolAddress((void**)&rc, g_rc);
    cudaGetSymbolAddress((void**)&rs, g_rs);

    const int GSMEM = 4 * 2 * STG_H * 2;   // 81920 bytes
    cudaFuncSetAttribute(mgemm_k<0, float>, cudaFuncAttributeMaxDynamicSharedMemorySize, GSMEM);
    cudaFuncSetAttribute(mgemm_k<1, float>, cudaFuncAttributeMaxDynamicSharedMemorySize, GSMEM);
    cudaFuncSetAttribute(mgemm_k<3, __half>, cudaFuncAttributeMaxDynamicSharedMemorySize, GSMEM);

    // weight transposes (+fp16 rounding)
    size_t oLS = (size_t)QKVD * DM;
    transpose_k<<<dim3(QKD/32, DM/32, NL), 256>>>(wq, wqkvT,            DM, QKD, (size_t)DM*QKD, oLS, 1, 0);
    transpose_k<<<dim3(KVD/32, DM/32, NL), 256>>>(wk, wqkvT + (size_t)QKD*DM,       DM, KVD, (size_t)DM*KVD, oLS, 1, 0);
    transpose_k<<<dim3(KVD/32, DM/32, NL), 256>>>(wv, wqkvT + (size_t)(QKD+KVD)*DM, DM, KVD, (size_t)DM*KVD, oLS, 1, 0);
    transpose_k<<<dim3(DM/32, QKD/32, NL), 256>>>(wo, woT, QKD, DM, (size_t)QKD*DM, (size_t)DM*QKD, 1, 0);
    transpose_k<<<dim3(IFF/32, DM/32, NL), 256>>>(wg, wguT, DM, IFF, (size_t)DM*IFF, (size_t)NGU*DM, 2, 0);
    transpose_k<<<dim3(IFF/32, DM/32, NL), 256>>>(wu, wguT, DM, IFF, (size_t)DM*IFF, (size_t)NGU*DM, 2, 1);
    transpose_k<<<dim3(DM/32, IFF/32, NL), 256>>>(wd, wdT, IFF, DM, (size_t)IFF*DM, (size_t)DM*IFF, 1, 0);
    biaspack_k<<<(NL*QKVD + 255)/256, 256>>>(bq, bk, bv, bqkv);
    ropetab_k<<<SEQ, 32>>>(rc, rs);

    int nx = ROWS * DM;
    copy_k<<<(nx + 255) / 256, 256>>>(x, emb, nx);

    dim3 gQKV(QKVD / 128, ROWS / 128);   // (9, 32)
    dim3 gDM (DM   / 128, ROWS / 128);   // (7, 32)
    dim3 gGU (NGU  / 128, ROWS / 128);   // (76, 32)
    dim3 gAt (SEQ / 128, NHQ, BSZ);      // (16, 14, 2)

    for (int l = 0; l < NL; l++) {
        rmsnorm_k<__half><<<ROWS, 256>>>(x, ln1 + (size_t)l * DM, h);

        mgemm_k<0, float><<<gQKV, 256, GSMEM>>>(h, wqkvT + (size_t)l * QKVD * DM,
                                                bqkv + (size_t)l * QKVD, qkv,
                                                ROWS, QKVD, DM);

        attn_k<<<gAt, 256>>>(qkv, tt, am, rc, rs, ao);

        mgemm_k<1, float><<<gDM, 256, GSMEM>>>(ao, woT + (size_t)l * DM * QKD,
                                               nullptr, x, ROWS, DM, QKD);

        rmsnorm_k<__half><<<ROWS, 256>>>(x, ln2 + (size_t)l * DM, h);

        mgemm_k<3, __half><<<gGU, 256, GSMEM>>>(h, wguT + (size_t)l * NGU * DM,
                                                nullptr, up, ROWS, NGU, DM);
        mgemm_k<1, float><<<gDM, 256, GSMEM>>>(up, wdT + (size_t)l * DM * IFF,
                                               nullptr, x, ROWS, DM, IFF);
    }

    rmsnorm_k<float><<<ROWS, 256>>>(x, lnf, (float*)d_out);
}